// round 10
// baseline (speedup 1.0000x reference)
#include <cuda_runtime.h>
#include <cuda_bf16.h>
#include <cstdint>

#define NAGENTS 32768
#define HDIM    256
#define ODIM    64
#define NGROUPS 1024
#define GSIZE   32
#define TSTEPS  (NAGENTS + 1)
#define ZROWS   1026   /* 1024 pooled + goal + zero-feat row */

// ---------------- device scratch (allocation-free) ----------------
__device__ float g_X[NAGENTS * HDIM];
__device__ float g_Y[NAGENTS * HDIM];
__device__ float g_R[ZROWS * HDIM];          // rows: pooled[0..1023], goal_emb, zeros
__device__ float g_zs[ZROWS * 1024];         // distinct input projections (+bias)
__device__ float g_hs[TSTEPS * HDIM];        // all hidden states
__device__ int   g_rowidx[NAGENTS];

// ---------------- PTX helpers ----------------
__device__ __forceinline__ uint32_t smem_u32(const void* p) {
    return (uint32_t)__cvta_generic_to_shared(p);
}
__device__ __forceinline__ uint32_t mapa_u32(uint32_t addr, uint32_t rank) {
    uint32_t r;
    asm("mapa.shared::cluster.u32 %0, %1, %2;" : "=r"(r) : "r"(addr), "r"(rank));
    return r;
}
__device__ __forceinline__ void st_async_b32(uint32_t daddr, uint32_t val, uint32_t dbar) {
    asm volatile("st.async.shared::cluster.mbarrier::complete_tx::bytes.b32 [%0], %1, [%2];"
                 :: "r"(daddr), "r"(val), "r"(dbar) : "memory");
}
__device__ __forceinline__ void mbar_init(uint32_t addr, uint32_t cnt) {
    asm volatile("mbarrier.init.shared.b64 [%0], %1;" :: "r"(addr), "r"(cnt) : "memory");
}
__device__ __forceinline__ void mbar_arrive_expect_tx(uint32_t addr, uint32_t bytes) {
    asm volatile("mbarrier.arrive.expect_tx.shared.b64 _, [%0], %1;"
                 :: "r"(addr), "r"(bytes) : "memory");
}
// CTA-scope acquire wait: st.async commits remote data to OUR smem before
// complete_tx is counted; acquire.cta orders our subsequent ld.shared.
__device__ __forceinline__ void mbar_wait(uint32_t addr, uint32_t parity) {
    asm volatile(
        "{\n\t.reg .pred P;\n\t"
        "WL_%=:\n\t"
        "mbarrier.try_wait.parity.acquire.cta.shared::cta.b64 P, [%0], %1, 0x989680;\n\t"
        "@P bra.uni WD_%=;\n\t"
        "bra.uni WL_%=;\n\t"
        "WD_%=:\n\t}"
        :: "r"(addr), "r"(parity) : "memory");
}
__device__ __forceinline__ uint32_t ctarank() {
    uint32_t r; asm("mov.u32 %0, %%cluster_ctarank;" : "=r"(r)); return r;
}
__device__ __forceinline__ float fsig(float x) {
    return __fdividef(1.0f, 1.0f + __expf(-x));
}
__device__ __forceinline__ float ftanh(float x) {
    float e = __expf(-2.0f * x);
    return __fdividef(1.0f - e, 1.0f + e);
}
// packed f32x2 FMA (SASS FFMA2 — only reachable via PTX)
#define FFMA2(acc, a, b) \
    asm("fma.rn.f32x2 %0, %1, %2, %3;" : "=l"(acc) : "l"(a), "l"(b), "l"(acc))
__device__ __forceinline__ unsigned long long pack_f32x2(float lo, float hi) {
    unsigned long long r;
    asm("mov.b64 %0, {%1, %2};" : "=l"(r) : "r"(__float_as_uint(lo)), "r"(__float_as_uint(hi)));
    return r;
}
__device__ __forceinline__ float2 unpack_f32x2(unsigned long long v) {
    uint32_t lo, hi;
    asm("mov.b64 {%0, %1}, %2;" : "=r"(lo), "=r"(hi) : "l"(v));
    return make_float2(__uint_as_float(lo), __uint_as_float(hi));
}

// ---------------- goal embedding ----------------
__global__ void k_goal(const float* __restrict__ goal, const float* __restrict__ W,
                       const float* __restrict__ b, float* __restrict__ R) {
    __shared__ float gs[HDIM];
    int j = threadIdx.x;
    gs[j] = goal[j];
    __syncthreads();
    float acc = 0.f;
    #pragma unroll 8
    for (int k = 0; k < HDIM; k++) acc = fmaf(gs[k], W[k * HDIM + j], acc);
    R[1024 * HDIM + j] = fmaxf(acc + b[j], 0.f);
    R[1025 * HDIM + j] = 0.f;
}

// ---------------- rowidx ----------------
__global__ void k_rowidx_init(int* __restrict__ ri) {
    int i = blockIdx.x * blockDim.x + threadIdx.x;
    if (i < NAGENTS) ri[i] = 1025;
}
__global__ void k_rowidx_scatter(const int* __restrict__ groups, int* __restrict__ ri) {
    int e = blockIdx.x * blockDim.x + threadIdx.x;
    if (e < NGROUPS * GSIZE) ri[groups[e]] = e >> 5;
}

// ---------------- group aggregate ----------------
template <int GATHER>
__global__ void k_group(const float* __restrict__ src, const int* __restrict__ groups,
                        float* __restrict__ U) {
    __shared__ float rows[GSIZE][HDIM];
    __shared__ int   idx[GSIZE];
    int g = blockIdx.x, t = threadIdx.x;
    if (GATHER) {
        if (t < GSIZE) idx[t] = groups[g * GSIZE + t];
        __syncthreads();
    }
    #pragma unroll 4
    for (int m = 0; m < GSIZE; m++) {
        int r = GATHER ? idx[m] : (g * GSIZE + m);
        rows[m][t] = src[r * HDIM + t];
    }
    __syncthreads();
    float s = 0.f;
    #pragma unroll
    for (int m = 0; m < GSIZE; m++) s += rows[m][t];
    const float inv = 1.0f / 33.0f;
    #pragma unroll 4
    for (int m = 0; m < GSIZE; m++)
        U[(g * GSIZE + m) * HDIM + t] = (rows[m][t] + s) * inv;
}

// ---------------- pool ----------------
__global__ void k_pool(const float* __restrict__ H2, float* __restrict__ R) {
    int g = blockIdx.x, t = threadIdx.x;
    float s = 0.f;
    #pragma unroll
    for (int m = 0; m < GSIZE; m++) s += H2[(g * GSIZE + m) * HDIM + t];
    R[g * HDIM + t] = s * (1.0f / 32.0f);
}

// ---------------- tiled SGEMM: C = act(A[M,K]@B[K,N] + bias) ----------------
__global__ __launch_bounds__(256) void k_gemm(
    const float* __restrict__ A, const float* __restrict__ B,
    const float* __restrict__ bias, float* __restrict__ C,
    int M, int N, int K, int doRelu)
{
    __shared__ float As[64][20];
    __shared__ float Bs[16][64];
    int t = threadIdx.x;
    int tx = t & 15, ty = t >> 4;
    int bm = blockIdx.y * 64, bn = blockIdx.x * 64;
    int row0 = ty * 4, col0 = tx * 4;
    float acc[4][4];
    #pragma unroll
    for (int i = 0; i < 4; i++)
        #pragma unroll
        for (int j = 0; j < 4; j++) acc[i][j] = 0.f;

    int am = t >> 2, ak4 = (t & 3) * 4;
    for (int kb = 0; kb < K; kb += 16) {
        float4 av = make_float4(0.f, 0.f, 0.f, 0.f);
        if (bm + am < M)
            av = *reinterpret_cast<const float4*>(&A[(size_t)(bm + am) * K + kb + ak4]);
        *reinterpret_cast<float4*>(&As[am][ak4]) = av;
        #pragma unroll
        for (int i = 0; i < 4; i++) {
            int e = t + i * 256;
            int k = e >> 6, n = e & 63;
            Bs[k][n] = B[(size_t)(kb + k) * N + bn + n];
        }
        __syncthreads();
        #pragma unroll
        for (int k = 0; k < 16; k++) {
            float a0 = As[row0 + 0][k], a1 = As[row0 + 1][k];
            float a2 = As[row0 + 2][k], a3 = As[row0 + 3][k];
            float4 bv = *reinterpret_cast<const float4*>(&Bs[k][col0]);
            acc[0][0] = fmaf(a0, bv.x, acc[0][0]); acc[0][1] = fmaf(a0, bv.y, acc[0][1]);
            acc[0][2] = fmaf(a0, bv.z, acc[0][2]); acc[0][3] = fmaf(a0, bv.w, acc[0][3]);
            acc[1][0] = fmaf(a1, bv.x, acc[1][0]); acc[1][1] = fmaf(a1, bv.y, acc[1][1]);
            acc[1][2] = fmaf(a1, bv.z, acc[1][2]); acc[1][3] = fmaf(a1, bv.w, acc[1][3]);
            acc[2][0] = fmaf(a2, bv.x, acc[2][0]); acc[2][1] = fmaf(a2, bv.y, acc[2][1]);
            acc[2][2] = fmaf(a2, bv.z, acc[2][2]); acc[2][3] = fmaf(a2, bv.w, acc[2][3]);
            acc[3][0] = fmaf(a3, bv.x, acc[3][0]); acc[3][1] = fmaf(a3, bv.y, acc[3][1]);
            acc[3][2] = fmaf(a3, bv.z, acc[3][2]); acc[3][3] = fmaf(a3, bv.w, acc[3][3]);
        }
        __syncthreads();
    }
    #pragma unroll
    for (int i = 0; i < 4; i++) {
        int r = bm + row0 + i;
        if (r >= M) break;
        #pragma unroll
        for (int j = 0; j < 4; j++) {
            float v = acc[i][j] + bias[bn + col0 + j];
            if (doRelu) v = fmaxf(v, 0.f);
            C[(size_t)r * N + bn + col0 + j] = v;
        }
    }
}

// ---------------- persistent 16-CTA-cluster LSTM, warp-autonomous steps ----------------
// CTA r owns h indices [r*16, r*16+16); warp w (0..15) owns h index base+w entirely:
//   lane group (l>>3) = gate (i,f,g,o), lane covers k in [ (l&7)*32, +32 ).
// No __syncthreads in the loop; 7 shfl collapse the reduce; all lanes compute c/h
// redundantly; lanes 0..15 fan h out to the 16 CTAs via st.async.
// smem: 2 h buffers (8 padded slices x 36 words) + 2 mbarriers.
#define HPAD    36
#define HBUFW   (8 * HPAD)          /* 288 words */
#define HBYTES  (HBUFW * 4)         /* 1152 B    */
#define BAROFF  (2 * HBYTES)        /* 2304      */
#define SMBYTES (BAROFF + 16)

__global__ __launch_bounds__(512, 1)
void k_lstm(const float* __restrict__ zs, const int* __restrict__ rowidx,
            const float* __restrict__ W_hh, float* __restrict__ hs)
{
    __shared__ __align__(16) unsigned char sm[SMBYTES];
    float* smf = reinterpret_cast<float*>(sm);

    const int t  = threadIdx.x;
    const int l  = t & 31;
    const int w  = t >> 5;              // warp = owned h col 0..15
    const int gate = l >> 3;            // lane group -> gate
    const int gl   = l & 7;             // lane within group
    const uint32_t rank = ctarank();
    const int base = rank * 16;
    const int gcol = gate * 256 + base + w;
    const int k0   = gl * 32;           // this lane's k window

    // resident packed W_hh: 16 f32x2 (32 k values for this (gate,col))
    unsigned long long w2[16];
    #pragma unroll
    for (int q = 0; q < 16; q++)
        w2[q] = pack_f32x2(W_hh[(size_t)(k0 + 2 * q) * 1024 + gcol],
                           W_hh[(size_t)(k0 + 2 * q + 1) * 1024 + gcol]);

    // zero both h buffers (incl. padding)
    for (int i = t; i < 2 * HBUFW; i += 512) smf[i] = 0.f;

    const uint32_t smb = smem_u32(sm);
    if (t == 0) {
        mbar_init(smb + BAROFF, 1);
        mbar_init(smb + BAROFF + 8, 1);
        mbar_arrive_expect_tx(smb + BAROFF, 1024);      // 16 CTAs x 16 floats
        mbar_arrive_expect_tx(smb + BAROFF + 8, 1024);
        asm volatile("fence.mbarrier_init.release.cluster;" ::: "memory");
    }
    __syncthreads();
    asm volatile("barrier.cluster.arrive.aligned;" ::: "memory");
    asm volatile("barrier.cluster.wait.aligned;" ::: "memory");

    // fan-out: lane l (<16) sends to rank l
    uint32_t rdst = 0;
    if (l < 16) rdst = mapa_u32(smb, (uint32_t)l);
    // padded word offset of h index (base+w) inside any h buffer
    const int hidx = base + w;
    const uint32_t myoff = 4u * ((uint32_t)(hidx >> 5) * HPAD + (uint32_t)(hidx & 31));

    float c = 0.f;                 // cell state (replicated across the warp)
    uint32_t ph0 = 0, ph1 = 0;

    for (int step = 0; step < TSTEPS; step++) {
        // prefetch this gate's z value (independent of h; hides L2 behind the wait)
        int row = (step == NAGENTS) ? 1024 : __ldg(&rowidx[step]);
        float z = __ldg(&zs[(size_t)row * 1024 + gcol]);

        const int buf = step & 1;
        if (step > 0) {            // wait for h(step-1) fan-in (CTA-scope acquire)
            if (buf) { mbar_wait(smb + BAROFF + 8, ph1); ph1 ^= 1; }
            else     { mbar_wait(smb + BAROFF, ph0); ph0 ^= 1; }
            if (t == 0) mbar_arrive_expect_tx(smb + BAROFF + (buf ? 8 : 0), 1024);
        }

        // matvec: lane covers k0..k0+31 (slice gl; 144B-strided slices -> conflict-free)
        const ulonglong2* hp = reinterpret_cast<const ulonglong2*>(
            sm + buf * HBYTES + gl * (HPAD * 4));
        unsigned long long a0 = 0ull, a1 = 0ull;
        #pragma unroll
        for (int q = 0; q < 4; q++) {
            ulonglong2 ha = hp[2 * q];
            ulonglong2 hb = hp[2 * q + 1];
            FFMA2(a0, ha.x, w2[4 * q + 0]);
            FFMA2(a1, ha.y, w2[4 * q + 1]);
            FFMA2(a0, hb.x, w2[4 * q + 2]);
            FFMA2(a1, hb.y, w2[4 * q + 3]);
        }
        float2 f0 = unpack_f32x2(a0), f1 = unpack_f32x2(a1);
        float v = (f0.x + f0.y) + (f1.x + f1.y);
        // reduce over the 8 lanes of this gate group
        v += __shfl_xor_sync(0xffffffffu, v, 1);
        v += __shfl_xor_sync(0xffffffffu, v, 2);
        v += __shfl_xor_sync(0xffffffffu, v, 4);
        v += z;                                    // every lane: full gate pre-activation
        // broadcast the 4 gate sums to all lanes
        float zi = __shfl_sync(0xffffffffu, v, 0);
        float zf = __shfl_sync(0xffffffffu, v, 8);
        float zg = __shfl_sync(0xffffffffu, v, 16);
        float zo = __shfl_sync(0xffffffffu, v, 24);

        c = fsig(zf) * c + fsig(zi) * ftanh(zg);
        float h = fsig(zo) * ftanh(c);

        if (l == 16) hs[step * HDIM + hidx] = h;
        if (l < 16 && step + 1 < TSTEPS) {     // fan out h to all 16 CTAs
            uint32_t nb = (uint32_t)((step + 1) & 1);
            st_async_b32(rdst + nb * HBYTES + myoff, __float_as_uint(h),
                         rdst + BAROFF + nb * 8u);
        }
    }
}

// ---------------- output: softmax(hs@W_act + b_act) ----------------
__global__ __launch_bounds__(256) void k_out(const float* __restrict__ hs,
                                             const float* __restrict__ W,
                                             const float* __restrict__ b,
                                             float* __restrict__ out) {
    __shared__ float hrow[8][HDIM];
    int warp = threadIdx.x >> 5, lane = threadIdx.x & 31;
    int row = blockIdx.x * 8 + warp;
    if (row >= TSTEPS) return;
    #pragma unroll
    for (int q = 0; q < 8; q++)
        hrow[warp][lane + q * 32] = hs[row * HDIM + lane + q * 32];
    __syncwarp();
    int c0 = lane, c1 = lane + 32;
    float acc0 = b[c0], acc1 = b[c1];
    #pragma unroll 8
    for (int k = 0; k < HDIM; k++) {
        float h = hrow[warp][k];
        acc0 = fmaf(h, __ldg(&W[k * ODIM + c0]), acc0);
        acc1 = fmaf(h, __ldg(&W[k * ODIM + c1]), acc1);
    }
    float m = fmaxf(acc0, acc1);
    #pragma unroll
    for (int s = 16; s > 0; s >>= 1) m = fmaxf(m, __shfl_xor_sync(0xffffffffu, m, s));
    float e0 = __expf(acc0 - m), e1 = __expf(acc1 - m);
    float s = e0 + e1;
    #pragma unroll
    for (int d = 16; d > 0; d >>= 1) s += __shfl_xor_sync(0xffffffffu, s, d);
    float inv = __fdividef(1.0f, s);
    out[row * ODIM + c0] = e0 * inv;
    out[row * ODIM + c1] = e1 * inv;
}

// ---------------- launch ----------------
extern "C" void kernel_launch(void* const* d_in, const int* in_sizes, int n_in,
                              void* d_out, int out_size) {
    const float* agent_state = (const float*)d_in[0];
    const float* goal_state  = (const float*)d_in[1];
    const int*   groups      = (const int*)  d_in[2];
    const float* W_goal      = (const float*)d_in[3];
    const float* b_goal      = (const float*)d_in[4];
    const float* W_g1        = (const float*)d_in[5];
    const float* b_g1        = (const float*)d_in[6];
    const float* W_g2        = (const float*)d_in[7];
    const float* b_g2        = (const float*)d_in[8];
    const float* W_ih        = (const float*)d_in[9];
    const float* W_hh        = (const float*)d_in[10];
    const float* b_lstm      = (const float*)d_in[11];
    const float* W_act       = (const float*)d_in[12];
    const float* b_act       = (const float*)d_in[13];
    float* out = (float*)d_out;

    float *X, *Y, *R, *ZS, *HS; int* RI;
    cudaGetSymbolAddress((void**)&X,  g_X);
    cudaGetSymbolAddress((void**)&Y,  g_Y);
    cudaGetSymbolAddress((void**)&R,  g_R);
    cudaGetSymbolAddress((void**)&ZS, g_zs);
    cudaGetSymbolAddress((void**)&HS, g_hs);
    cudaGetSymbolAddress((void**)&RI, g_rowidx);

    k_goal<<<1, 256>>>(goal_state, W_goal, b_goal, R);
    k_rowidx_init<<<NAGENTS / 256, 256>>>(RI);
    k_rowidx_scatter<<<NGROUPS * GSIZE / 256, 256>>>(groups, RI);

    k_group<1><<<NGROUPS, 256>>>(agent_state, groups, X);                 // U1
    k_gemm<<<dim3(4, 512), 256>>>(X, W_g1, b_g1, Y, NAGENTS, HDIM, HDIM, 1);   // H1
    k_group<0><<<NGROUPS, 256>>>(Y, nullptr, X);                          // U2
    k_gemm<<<dim3(4, 512), 256>>>(X, W_g2, b_g2, Y, NAGENTS, HDIM, HDIM, 1);   // H2
    k_pool<<<NGROUPS, 256>>>(Y, R);

    k_gemm<<<dim3(16, 17), 256>>>(R, W_ih, b_lstm, ZS, ZROWS, 1024, HDIM, 0);  // zs

    // 16-CTA cluster LSTM (nonportable cluster size)
    cudaFuncSetAttribute(k_lstm, cudaFuncAttributeNonPortableClusterSizeAllowed, 1);
    {
        cudaLaunchConfig_t cfg = {};
        cfg.gridDim  = dim3(16, 1, 1);
        cfg.blockDim = dim3(512, 1, 1);
        cfg.dynamicSmemBytes = 0;
        cfg.stream = 0;
        cudaLaunchAttribute at[1];
        at[0].id = cudaLaunchAttributeClusterDimension;
        at[0].val.clusterDim.x = 16;
        at[0].val.clusterDim.y = 1;
        at[0].val.clusterDim.z = 1;
        cfg.attrs = at;
        cfg.numAttrs = 1;
        cudaLaunchKernelEx(&cfg, k_lstm, (const float*)ZS, (const int*)RI, W_hh, (float*)HS);
    }

    k_out<<<(TSTEPS + 7) / 8, 256>>>(HS, W_act, b_act, out);
}

// round 11
// speedup vs baseline: 1.8328x; 1.8328x over previous
#include <cuda_runtime.h>
#include <cuda_bf16.h>
#include <cstdint>

#define NAGENTS 32768
#define HDIM    256
#define ODIM    64
#define NGROUPS 1024
#define GSIZE   32
#define TSTEPS  (NAGENTS + 1)
#define ZROWS   1026   /* 1024 pooled + goal + zero-feat row */

// ---------------- device scratch (allocation-free) ----------------
__device__ float g_X[NAGENTS * HDIM];
__device__ float g_Y[NAGENTS * HDIM];
__device__ float g_R[ZROWS * HDIM];          // rows: pooled[0..1023], goal_emb, zeros
__device__ float g_zs[ZROWS * 1024];         // distinct input projections (+bias)
__device__ float g_hs[TSTEPS * HDIM];        // all hidden states
__device__ int   g_rowidx[NAGENTS];

// ---------------- PTX helpers ----------------
__device__ __forceinline__ uint32_t smem_u32(const void* p) {
    return (uint32_t)__cvta_generic_to_shared(p);
}
__device__ __forceinline__ uint32_t mapa_u32(uint32_t addr, uint32_t rank) {
    uint32_t r;
    asm("mapa.shared::cluster.u32 %0, %1, %2;" : "=r"(r) : "r"(addr), "r"(rank));
    return r;
}
__device__ __forceinline__ void st_async_b32(uint32_t daddr, uint32_t val, uint32_t dbar) {
    asm volatile("st.async.shared::cluster.mbarrier::complete_tx::bytes.b32 [%0], %1, [%2];"
                 :: "r"(daddr), "r"(val), "r"(dbar) : "memory");
}
__device__ __forceinline__ void mbar_init(uint32_t addr, uint32_t cnt) {
    asm volatile("mbarrier.init.shared.b64 [%0], %1;" :: "r"(addr), "r"(cnt) : "memory");
}
__device__ __forceinline__ void mbar_arrive_expect_tx(uint32_t addr, uint32_t bytes) {
    asm volatile("mbarrier.arrive.expect_tx.shared.b64 _, [%0], %1;"
                 :: "r"(addr), "r"(bytes) : "memory");
}
// CTA-scope acquire wait: st.async commits remote data to OUR smem before
// complete_tx is counted; acquire.cta orders our subsequent ld.shared.
__device__ __forceinline__ void mbar_wait(uint32_t addr, uint32_t parity) {
    asm volatile(
        "{\n\t.reg .pred P;\n\t"
        "WL_%=:\n\t"
        "mbarrier.try_wait.parity.acquire.cta.shared::cta.b64 P, [%0], %1, 0x989680;\n\t"
        "@P bra.uni WD_%=;\n\t"
        "bra.uni WL_%=;\n\t"
        "WD_%=:\n\t}"
        :: "r"(addr), "r"(parity) : "memory");
}
__device__ __forceinline__ uint32_t ctarank() {
    uint32_t r; asm("mov.u32 %0, %%cluster_ctarank;" : "=r"(r)); return r;
}
__device__ __forceinline__ float fsig(float x) {
    return __fdividef(1.0f, 1.0f + __expf(-x));
}
__device__ __forceinline__ float ftanh(float x) {
    float e = __expf(-2.0f * x);
    return __fdividef(1.0f - e, 1.0f + e);
}
// packed f32x2 FMA (SASS FFMA2 — only reachable via PTX)
#define FFMA2(acc, a, b) \
    asm("fma.rn.f32x2 %0, %1, %2, %3;" : "=l"(acc) : "l"(a), "l"(b), "l"(acc))
__device__ __forceinline__ unsigned long long pack_f32x2(float lo, float hi) {
    unsigned long long r;
    asm("mov.b64 %0, {%1, %2};" : "=l"(r) : "r"(__float_as_uint(lo)), "r"(__float_as_uint(hi)));
    return r;
}
__device__ __forceinline__ float2 unpack_f32x2(unsigned long long v) {
    uint32_t lo, hi;
    asm("mov.b64 {%0, %1}, %2;" : "=r"(lo), "=r"(hi) : "l"(v));
    return make_float2(__uint_as_float(lo), __uint_as_float(hi));
}

// ---------------- goal embedding ----------------
__global__ void k_goal(const float* __restrict__ goal, const float* __restrict__ W,
                       const float* __restrict__ b, float* __restrict__ R) {
    __shared__ float gs[HDIM];
    int j = threadIdx.x;
    gs[j] = goal[j];
    __syncthreads();
    float acc = 0.f;
    #pragma unroll 8
    for (int k = 0; k < HDIM; k++) acc = fmaf(gs[k], W[k * HDIM + j], acc);
    R[1024 * HDIM + j] = fmaxf(acc + b[j], 0.f);
    R[1025 * HDIM + j] = 0.f;
}

// ---------------- rowidx ----------------
__global__ void k_rowidx_init(int* __restrict__ ri) {
    int i = blockIdx.x * blockDim.x + threadIdx.x;
    if (i < NAGENTS) ri[i] = 1025;
}
__global__ void k_rowidx_scatter(const int* __restrict__ groups, int* __restrict__ ri) {
    int e = blockIdx.x * blockDim.x + threadIdx.x;
    if (e < NGROUPS * GSIZE) ri[groups[e]] = e >> 5;
}

// ---------------- group aggregate ----------------
template <int GATHER>
__global__ void k_group(const float* __restrict__ src, const int* __restrict__ groups,
                        float* __restrict__ U) {
    __shared__ float rows[GSIZE][HDIM];
    __shared__ int   idx[GSIZE];
    int g = blockIdx.x, t = threadIdx.x;
    if (GATHER) {
        if (t < GSIZE) idx[t] = groups[g * GSIZE + t];
        __syncthreads();
    }
    #pragma unroll 4
    for (int m = 0; m < GSIZE; m++) {
        int r = GATHER ? idx[m] : (g * GSIZE + m);
        rows[m][t] = src[r * HDIM + t];
    }
    __syncthreads();
    float s = 0.f;
    #pragma unroll
    for (int m = 0; m < GSIZE; m++) s += rows[m][t];
    const float inv = 1.0f / 33.0f;
    #pragma unroll 4
    for (int m = 0; m < GSIZE; m++)
        U[(g * GSIZE + m) * HDIM + t] = (rows[m][t] + s) * inv;
}

// ---------------- pool ----------------
__global__ void k_pool(const float* __restrict__ H2, float* __restrict__ R) {
    int g = blockIdx.x, t = threadIdx.x;
    float s = 0.f;
    #pragma unroll
    for (int m = 0; m < GSIZE; m++) s += H2[(g * GSIZE + m) * HDIM + t];
    R[g * HDIM + t] = s * (1.0f / 32.0f);
}

// ---------------- tiled SGEMM: C = act(A[M,K]@B[K,N] + bias) ----------------
__global__ __launch_bounds__(256) void k_gemm(
    const float* __restrict__ A, const float* __restrict__ B,
    const float* __restrict__ bias, float* __restrict__ C,
    int M, int N, int K, int doRelu)
{
    __shared__ float As[64][20];
    __shared__ float Bs[16][64];
    int t = threadIdx.x;
    int tx = t & 15, ty = t >> 4;
    int bm = blockIdx.y * 64, bn = blockIdx.x * 64;
    int row0 = ty * 4, col0 = tx * 4;
    float acc[4][4];
    #pragma unroll
    for (int i = 0; i < 4; i++)
        #pragma unroll
        for (int j = 0; j < 4; j++) acc[i][j] = 0.f;

    int am = t >> 2, ak4 = (t & 3) * 4;
    for (int kb = 0; kb < K; kb += 16) {
        float4 av = make_float4(0.f, 0.f, 0.f, 0.f);
        if (bm + am < M)
            av = *reinterpret_cast<const float4*>(&A[(size_t)(bm + am) * K + kb + ak4]);
        *reinterpret_cast<float4*>(&As[am][ak4]) = av;
        #pragma unroll
        for (int i = 0; i < 4; i++) {
            int e = t + i * 256;
            int k = e >> 6, n = e & 63;
            Bs[k][n] = B[(size_t)(kb + k) * N + bn + n];
        }
        __syncthreads();
        #pragma unroll
        for (int k = 0; k < 16; k++) {
            float a0 = As[row0 + 0][k], a1 = As[row0 + 1][k];
            float a2 = As[row0 + 2][k], a3 = As[row0 + 3][k];
            float4 bv = *reinterpret_cast<const float4*>(&Bs[k][col0]);
            acc[0][0] = fmaf(a0, bv.x, acc[0][0]); acc[0][1] = fmaf(a0, bv.y, acc[0][1]);
            acc[0][2] = fmaf(a0, bv.z, acc[0][2]); acc[0][3] = fmaf(a0, bv.w, acc[0][3]);
            acc[1][0] = fmaf(a1, bv.x, acc[1][0]); acc[1][1] = fmaf(a1, bv.y, acc[1][1]);
            acc[1][2] = fmaf(a1, bv.z, acc[1][2]); acc[1][3] = fmaf(a1, bv.w, acc[1][3]);
            acc[2][0] = fmaf(a2, bv.x, acc[2][0]); acc[2][1] = fmaf(a2, bv.y, acc[2][1]);
            acc[2][2] = fmaf(a2, bv.z, acc[2][2]); acc[2][3] = fmaf(a2, bv.w, acc[2][3]);
            acc[3][0] = fmaf(a3, bv.x, acc[3][0]); acc[3][1] = fmaf(a3, bv.y, acc[3][1]);
            acc[3][2] = fmaf(a3, bv.z, acc[3][2]); acc[3][3] = fmaf(a3, bv.w, acc[3][3]);
        }
        __syncthreads();
    }
    #pragma unroll
    for (int i = 0; i < 4; i++) {
        int r = bm + row0 + i;
        if (r >= M) break;
        #pragma unroll
        for (int j = 0; j < 4; j++) {
            float v = acc[i][j] + bias[bn + col0 + j];
            if (doRelu) v = fmaxf(v, 0.f);
            C[(size_t)r * N + bn + col0 + j] = v;
        }
    }
}

// ---------------- persistent 16-CTA-cluster LSTM (round-9 structure + z pipelined) ----------------
// CTA r owns hidden indices [r*16, r*16+16) and gate cols {g*256 + r*16 + j}.
// 512 threads: warp w lane l -> local col lc = w*4+(l&3) (64 cols), k-slice l>>2 (8x32k).
// smem: 2 h-buffers (8 padded slices x 36 words), 2 mbarriers, pa double-buffered.
// z gather (rowidx -> zs, dependent L2 loads) is software-pipelined ONE STEP AHEAD
// so its ~500-cyc chain is hidden under the full step instead of poking out.
#define HPAD    36
#define HBUFW   (8 * HPAD)          /* 288 words */
#define HBYTES  (HBUFW * 4)         /* 1152 B    */
#define BAROFF  (2 * HBYTES)        /* 2304      */
#define PAOFF   (BAROFF + 16)       /* 2320      */
#define SMBYTES (PAOFF + 2 * 64 * 4)

__global__ __launch_bounds__(512, 1)
void k_lstm(const float* __restrict__ zs, const int* __restrict__ rowidx,
            const float* __restrict__ W_hh, float* __restrict__ hs)
{
    __shared__ __align__(16) unsigned char sm[SMBYTES];
    float* smf = reinterpret_cast<float*>(sm);

    const int t = threadIdx.x;
    const int l = t & 31;
    const int w = t >> 5;
    const int lc   = w * 4 + (l & 3);   // local gate-col 0..63
    const int ksl  = l >> 2;            // k-slice 0..7 (32 k each)
    const int gate = lc >> 4;
    const int j    = lc & 15;
    const uint32_t rank = ctarank();
    const int base = rank * 16;
    const int gcol = gate * 256 + base + j;

    // resident packed W_hh slice: 16 f32x2 regs (32 k-values for this col)
    unsigned long long w2[16];
    #pragma unroll
    for (int q = 0; q < 16; q++)
        w2[q] = pack_f32x2(W_hh[(size_t)(ksl * 32 + 2 * q) * 1024 + gcol],
                           W_hh[(size_t)(ksl * 32 + 2 * q + 1) * 1024 + gcol]);

    // zero both h buffers (incl. padding)
    for (int i = t; i < 2 * HBUFW; i += 512) smf[i] = 0.f;

    const uint32_t smb = smem_u32(sm);
    if (t == 0) {
        mbar_init(smb + BAROFF, 1);
        mbar_init(smb + BAROFF + 8, 1);
        mbar_arrive_expect_tx(smb + BAROFF, 1024);      // 16 CTAs x 16 floats
        mbar_arrive_expect_tx(smb + BAROFF + 8, 1024);
        asm volatile("fence.mbarrier_init.release.cluster;" ::: "memory");
    }
    __syncthreads();
    asm volatile("barrier.cluster.arrive.aligned;" ::: "memory");
    asm volatile("barrier.cluster.wait.aligned;" ::: "memory");

    // fan-out: thread t<256 owns col hj=t&15, sends to rank t>>4 (16 lanes of a
    // half-warp -> same rank, contiguous words -> coalesced 64B DSMEM writes)
    const int hj = t & 15;
    uint32_t rdst = 0;
    if (t < 256) rdst = mapa_u32(smb, (uint32_t)(t >> 4));
    // padded word offset of my h value (global idx base+hj) inside any h buffer
    const uint32_t myoff = 4u * ((rank >> 1) * HPAD + (rank & 1) * 16 + (uint32_t)hj);

    float c = 0.f;                 // cell state for col base+hj (replicated x16 threads)
    uint32_t ph0 = 0, ph1 = 0;

    // ---- z pipeline prologue: load z for step 0 ----
    float z0 = 0.f, z1 = 0.f, z2 = 0.f, z3 = 0.f;
    if (t < 256) {
        int row = __ldg(&rowidx[0]);
        const float* zr = zs + (size_t)row * 1024 + base + hj;
        z0 = __ldg(zr);
        z1 = __ldg(zr + 256);
        z2 = __ldg(zr + 512);
        z3 = __ldg(zr + 768);
    }

    for (int step = 0; step < TSTEPS; step++) {
        // issue NEXT step's z gather now — consumed next iteration (~1 step later)
        float nz0 = 0.f, nz1 = 0.f, nz2 = 0.f, nz3 = 0.f;
        if (t < 256 && step + 1 < TSTEPS) {
            int nrow = (step + 1 == NAGENTS) ? 1024 : __ldg(&rowidx[step + 1]);
            const float* zr = zs + (size_t)nrow * 1024 + base + hj;
            nz0 = __ldg(zr);
            nz1 = __ldg(zr + 256);
            nz2 = __ldg(zr + 512);
            nz3 = __ldg(zr + 768);
        }

        const int buf = step & 1;
        if (step > 0) {            // wait for h(step-1) fan-in (CTA-scope acquire)
            if (buf) { mbar_wait(smb + BAROFF + 8, ph1); ph1 ^= 1; }
            else     { mbar_wait(smb + BAROFF, ph0); ph0 ^= 1; }
            if (t == 0) mbar_arrive_expect_tx(smb + BAROFF + (buf ? 8 : 0), 1024);
        }

        // matvec: 32 k for (col, slice); padded slices (144B apart) -> conflict-free LDS.128
        const ulonglong2* hp = reinterpret_cast<const ulonglong2*>(
            sm + buf * HBYTES + ksl * (HPAD * 4));
        unsigned long long a0 = 0ull, a1 = 0ull;
        #pragma unroll
        for (int q = 0; q < 4; q++) {
            ulonglong2 ha = hp[2 * q];
            ulonglong2 hb = hp[2 * q + 1];
            FFMA2(a0, ha.x, w2[4 * q + 0]);
            FFMA2(a1, ha.y, w2[4 * q + 1]);
            FFMA2(a0, hb.x, w2[4 * q + 2]);
            FFMA2(a1, hb.y, w2[4 * q + 3]);
        }
        float2 f0 = unpack_f32x2(a0), f1 = unpack_f32x2(a1);
        float v = (f0.x + f0.y) + (f1.x + f1.y);
        // reduce across the 8 k-slices (lane bits 2,3,4)
        v += __shfl_xor_sync(0xffffffffu, v, 4);
        v += __shfl_xor_sync(0xffffffffu, v, 8);
        v += __shfl_xor_sync(0xffffffffu, v, 16);
        if (l < 4) smf[(PAOFF >> 2) + buf * 64 + j * 4 + gate] = v;  // pa[buf][j][gate]
        __syncthreads();                                              // one bar per step

        if (t < 256) {
            float4 g4 = *reinterpret_cast<const float4*>(
                &smf[(PAOFF >> 2) + buf * 64 + hj * 4]);
            float zi = g4.x + z0, zf = g4.y + z1, zg = g4.z + z2, zo = g4.w + z3;
            c = fsig(zf) * c + fsig(zi) * ftanh(zg);
            float h = fsig(zo) * ftanh(c);
            if (t < 16) hs[step * HDIM + base + t] = h;
            if (step + 1 < TSTEPS) {       // each of 256 threads: one st.async
                uint32_t nb = (uint32_t)((step + 1) & 1);
                st_async_b32(rdst + nb * HBYTES + myoff, __float_as_uint(h),
                             rdst + BAROFF + nb * 8u);
            }
        }
        z0 = nz0; z1 = nz1; z2 = nz2; z3 = nz3;
    }
}

// ---------------- output: softmax(hs@W_act + b_act) ----------------
__global__ __launch_bounds__(256) void k_out(const float* __restrict__ hs,
                                             const float* __restrict__ W,
                                             const float* __restrict__ b,
                                             float* __restrict__ out) {
    __shared__ float hrow[8][HDIM];
    int warp = threadIdx.x >> 5, lane = threadIdx.x & 31;
    int row = blockIdx.x * 8 + warp;
    if (row >= TSTEPS) return;
    #pragma unroll
    for (int q = 0; q < 8; q++)
        hrow[warp][lane + q * 32] = hs[row * HDIM + lane + q * 32];
    __syncwarp();
    int c0 = lane, c1 = lane + 32;
    float acc0 = b[c0], acc1 = b[c1];
    #pragma unroll 8
    for (int k = 0; k < HDIM; k++) {
        float h = hrow[warp][k];
        acc0 = fmaf(h, __ldg(&W[k * ODIM + c0]), acc0);
        acc1 = fmaf(h, __ldg(&W[k * ODIM + c1]), acc1);
    }
    float m = fmaxf(acc0, acc1);
    #pragma unroll
    for (int s = 16; s > 0; s >>= 1) m = fmaxf(m, __shfl_xor_sync(0xffffffffu, m, s));
    float e0 = __expf(acc0 - m), e1 = __expf(acc1 - m);
    float s = e0 + e1;
    #pragma unroll
    for (int d = 16; d > 0; d >>= 1) s += __shfl_xor_sync(0xffffffffu, s, d);
    float inv = __fdividef(1.0f, s);
    out[row * ODIM + c0] = e0 * inv;
    out[row * ODIM + c1] = e1 * inv;
}

// ---------------- launch ----------------
extern "C" void kernel_launch(void* const* d_in, const int* in_sizes, int n_in,
                              void* d_out, int out_size) {
    const float* agent_state = (const float*)d_in[0];
    const float* goal_state  = (const float*)d_in[1];
    const int*   groups      = (const int*)  d_in[2];
    const float* W_goal      = (const float*)d_in[3];
    const float* b_goal      = (const float*)d_in[4];
    const float* W_g1        = (const float*)d_in[5];
    const float* b_g1        = (const float*)d_in[6];
    const float* W_g2        = (const float*)d_in[7];
    const float* b_g2        = (const float*)d_in[8];
    const float* W_ih        = (const float*)d_in[9];
    const float* W_hh        = (const float*)d_in[10];
    const float* b_lstm      = (const float*)d_in[11];
    const float* W_act       = (const float*)d_in[12];
    const float* b_act       = (const float*)d_in[13];
    float* out = (float*)d_out;

    float *X, *Y, *R, *ZS, *HS; int* RI;
    cudaGetSymbolAddress((void**)&X,  g_X);
    cudaGetSymbolAddress((void**)&Y,  g_Y);
    cudaGetSymbolAddress((void**)&R,  g_R);
    cudaGetSymbolAddress((void**)&ZS, g_zs);
    cudaGetSymbolAddress((void**)&HS, g_hs);
    cudaGetSymbolAddress((void**)&RI, g_rowidx);

    k_goal<<<1, 256>>>(goal_state, W_goal, b_goal, R);
    k_rowidx_init<<<NAGENTS / 256, 256>>>(RI);
    k_rowidx_scatter<<<NGROUPS * GSIZE / 256, 256>>>(groups, RI);

    k_group<1><<<NGROUPS, 256>>>(agent_state, groups, X);                 // U1
    k_gemm<<<dim3(4, 512), 256>>>(X, W_g1, b_g1, Y, NAGENTS, HDIM, HDIM, 1);   // H1
    k_group<0><<<NGROUPS, 256>>>(Y, nullptr, X);                          // U2
    k_gemm<<<dim3(4, 512), 256>>>(X, W_g2, b_g2, Y, NAGENTS, HDIM, HDIM, 1);   // H2
    k_pool<<<NGROUPS, 256>>>(Y, R);

    k_gemm<<<dim3(16, 17), 256>>>(R, W_ih, b_lstm, ZS, ZROWS, 1024, HDIM, 0);  // zs

    // 16-CTA cluster LSTM (nonportable cluster size)
    cudaFuncSetAttribute(k_lstm, cudaFuncAttributeNonPortableClusterSizeAllowed, 1);
    {
        cudaLaunchConfig_t cfg = {};
        cfg.gridDim  = dim3(16, 1, 1);
        cfg.blockDim = dim3(512, 1, 1);
        cfg.dynamicSmemBytes = 0;
        cfg.stream = 0;
        cudaLaunchAttribute at[1];
        at[0].id = cudaLaunchAttributeClusterDimension;
        at[0].val.clusterDim.x = 16;
        at[0].val.clusterDim.y = 1;
        at[0].val.clusterDim.z = 1;
        cfg.attrs = at;
        cfg.numAttrs = 1;
        cudaLaunchKernelEx(&cfg, k_lstm, (const float*)ZS, (const int*)RI, W_hh, (float*)HS);
    }

    k_out<<<(TSTEPS + 7) / 8, 256>>>(HS, W_act, b_act, out);
}

// round 12
// speedup vs baseline: 2.0236x; 1.1041x over previous
#include <cuda_runtime.h>
#include <cuda_bf16.h>
#include <cstdint>

#define NAGENTS 32768
#define HDIM    256
#define ODIM    64
#define NGROUPS 1024
#define GSIZE   32
#define TSTEPS  (NAGENTS + 1)
#define ZROWS   1026   /* 1024 pooled + goal + zero-feat row */

// ---------------- device scratch (allocation-free) ----------------
__device__ float g_X[NAGENTS * HDIM];
__device__ float g_Y[NAGENTS * HDIM];
__device__ float g_R[ZROWS * HDIM];          // rows: pooled[0..1023], goal_emb, zeros
__device__ float g_zs[ZROWS * 1024];         // distinct input projections (+bias)
__device__ float g_hs[TSTEPS * HDIM];        // all hidden states
__device__ int   g_rowidx[NAGENTS];

// ---------------- PTX helpers ----------------
__device__ __forceinline__ uint32_t smem_u32(const void* p) {
    return (uint32_t)__cvta_generic_to_shared(p);
}
__device__ __forceinline__ uint32_t mapa_u32(uint32_t addr, uint32_t rank) {
    uint32_t r;
    asm("mapa.shared::cluster.u32 %0, %1, %2;" : "=r"(r) : "r"(addr), "r"(rank));
    return r;
}
__device__ __forceinline__ void st_async_b32(uint32_t daddr, uint32_t val, uint32_t dbar) {
    asm volatile("st.async.shared::cluster.mbarrier::complete_tx::bytes.b32 [%0], %1, [%2];"
                 :: "r"(daddr), "r"(val), "r"(dbar) : "memory");
}
__device__ __forceinline__ void mbar_init(uint32_t addr, uint32_t cnt) {
    asm volatile("mbarrier.init.shared.b64 [%0], %1;" :: "r"(addr), "r"(cnt) : "memory");
}
__device__ __forceinline__ void mbar_arrive_expect_tx(uint32_t addr, uint32_t bytes) {
    asm volatile("mbarrier.arrive.expect_tx.shared.b64 _, [%0], %1;"
                 :: "r"(addr), "r"(bytes) : "memory");
}
// CTA-scope acquire wait: st.async commits remote data to OUR smem before
// complete_tx is counted; acquire.cta orders our subsequent ld.shared.
__device__ __forceinline__ void mbar_wait(uint32_t addr, uint32_t parity) {
    asm volatile(
        "{\n\t.reg .pred P;\n\t"
        "WL_%=:\n\t"
        "mbarrier.try_wait.parity.acquire.cta.shared::cta.b64 P, [%0], %1, 0x989680;\n\t"
        "@P bra.uni WD_%=;\n\t"
        "bra.uni WL_%=;\n\t"
        "WD_%=:\n\t}"
        :: "r"(addr), "r"(parity) : "memory");
}
__device__ __forceinline__ uint32_t ctarank() {
    uint32_t r; asm("mov.u32 %0, %%cluster_ctarank;" : "=r"(r)); return r;
}
// Fast gates via single-op MUFU.TANH (tanh.approx.f32, sm_75+; ~16 cyc vs ~45
// for the exp+div chain). sigmoid(x) = 0.5*tanh(x/2) + 0.5.
__device__ __forceinline__ float ftanh_fast(float x) {
    float y;
    asm("tanh.approx.f32 %0, %1;" : "=f"(y) : "f"(x));
    return y;
}
__device__ __forceinline__ float fsig_fast(float x) {
    float y;
    asm("tanh.approx.f32 %0, %1;" : "=f"(y) : "f"(x * 0.5f));
    return fmaf(0.5f, y, 0.5f);
}
// packed f32x2 FMA (SASS FFMA2 — only reachable via PTX)
#define FFMA2(acc, a, b) \
    asm("fma.rn.f32x2 %0, %1, %2, %3;" : "=l"(acc) : "l"(a), "l"(b), "l"(acc))
__device__ __forceinline__ unsigned long long pack_f32x2(float lo, float hi) {
    unsigned long long r;
    asm("mov.b64 %0, {%1, %2};" : "=l"(r) : "r"(__float_as_uint(lo)), "r"(__float_as_uint(hi)));
    return r;
}
__device__ __forceinline__ float2 unpack_f32x2(unsigned long long v) {
    uint32_t lo, hi;
    asm("mov.b64 {%0, %1}, %2;" : "=r"(lo), "=r"(hi) : "l"(v));
    return make_float2(__uint_as_float(lo), __uint_as_float(hi));
}

// ---------------- goal embedding ----------------
__global__ void k_goal(const float* __restrict__ goal, const float* __restrict__ W,
                       const float* __restrict__ b, float* __restrict__ R) {
    __shared__ float gs[HDIM];
    int j = threadIdx.x;
    gs[j] = goal[j];
    __syncthreads();
    float acc = 0.f;
    #pragma unroll 8
    for (int k = 0; k < HDIM; k++) acc = fmaf(gs[k], W[k * HDIM + j], acc);
    R[1024 * HDIM + j] = fmaxf(acc + b[j], 0.f);
    R[1025 * HDIM + j] = 0.f;
}

// ---------------- rowidx ----------------
__global__ void k_rowidx_init(int* __restrict__ ri) {
    int i = blockIdx.x * blockDim.x + threadIdx.x;
    if (i < NAGENTS) ri[i] = 1025;
}
__global__ void k_rowidx_scatter(const int* __restrict__ groups, int* __restrict__ ri) {
    int e = blockIdx.x * blockDim.x + threadIdx.x;
    if (e < NGROUPS * GSIZE) ri[groups[e]] = e >> 5;
}

// ---------------- group aggregate ----------------
template <int GATHER>
__global__ void k_group(const float* __restrict__ src, const int* __restrict__ groups,
                        float* __restrict__ U) {
    __shared__ float rows[GSIZE][HDIM];
    __shared__ int   idx[GSIZE];
    int g = blockIdx.x, t = threadIdx.x;
    if (GATHER) {
        if (t < GSIZE) idx[t] = groups[g * GSIZE + t];
        __syncthreads();
    }
    #pragma unroll 4
    for (int m = 0; m < GSIZE; m++) {
        int r = GATHER ? idx[m] : (g * GSIZE + m);
        rows[m][t] = src[r * HDIM + t];
    }
    __syncthreads();
    float s = 0.f;
    #pragma unroll
    for (int m = 0; m < GSIZE; m++) s += rows[m][t];
    const float inv = 1.0f / 33.0f;
    #pragma unroll 4
    for (int m = 0; m < GSIZE; m++)
        U[(g * GSIZE + m) * HDIM + t] = (rows[m][t] + s) * inv;
}

// ---------------- pool ----------------
__global__ void k_pool(const float* __restrict__ H2, float* __restrict__ R) {
    int g = blockIdx.x, t = threadIdx.x;
    float s = 0.f;
    #pragma unroll
    for (int m = 0; m < GSIZE; m++) s += H2[(g * GSIZE + m) * HDIM + t];
    R[g * HDIM + t] = s * (1.0f / 32.0f);
}

// ---------------- tiled SGEMM: C = act(A[M,K]@B[K,N] + bias) ----------------
__global__ __launch_bounds__(256) void k_gemm(
    const float* __restrict__ A, const float* __restrict__ B,
    const float* __restrict__ bias, float* __restrict__ C,
    int M, int N, int K, int doRelu)
{
    __shared__ float As[64][20];
    __shared__ float Bs[16][64];
    int t = threadIdx.x;
    int tx = t & 15, ty = t >> 4;
    int bm = blockIdx.y * 64, bn = blockIdx.x * 64;
    int row0 = ty * 4, col0 = tx * 4;
    float acc[4][4];
    #pragma unroll
    for (int i = 0; i < 4; i++)
        #pragma unroll
        for (int j = 0; j < 4; j++) acc[i][j] = 0.f;

    int am = t >> 2, ak4 = (t & 3) * 4;
    for (int kb = 0; kb < K; kb += 16) {
        float4 av = make_float4(0.f, 0.f, 0.f, 0.f);
        if (bm + am < M)
            av = *reinterpret_cast<const float4*>(&A[(size_t)(bm + am) * K + kb + ak4]);
        *reinterpret_cast<float4*>(&As[am][ak4]) = av;
        #pragma unroll
        for (int i = 0; i < 4; i++) {
            int e = t + i * 256;
            int k = e >> 6, n = e & 63;
            Bs[k][n] = B[(size_t)(kb + k) * N + bn + n];
        }
        __syncthreads();
        #pragma unroll
        for (int k = 0; k < 16; k++) {
            float a0 = As[row0 + 0][k], a1 = As[row0 + 1][k];
            float a2 = As[row0 + 2][k], a3 = As[row0 + 3][k];
            float4 bv = *reinterpret_cast<const float4*>(&Bs[k][col0]);
            acc[0][0] = fmaf(a0, bv.x, acc[0][0]); acc[0][1] = fmaf(a0, bv.y, acc[0][1]);
            acc[0][2] = fmaf(a0, bv.z, acc[0][2]); acc[0][3] = fmaf(a0, bv.w, acc[0][3]);
            acc[1][0] = fmaf(a1, bv.x, acc[1][0]); acc[1][1] = fmaf(a1, bv.y, acc[1][1]);
            acc[1][2] = fmaf(a1, bv.z, acc[1][2]); acc[1][3] = fmaf(a1, bv.w, acc[1][3]);
            acc[2][0] = fmaf(a2, bv.x, acc[2][0]); acc[2][1] = fmaf(a2, bv.y, acc[2][1]);
            acc[2][2] = fmaf(a2, bv.z, acc[2][2]); acc[2][3] = fmaf(a2, bv.w, acc[2][3]);
            acc[3][0] = fmaf(a3, bv.x, acc[3][0]); acc[3][1] = fmaf(a3, bv.y, acc[3][1]);
            acc[3][2] = fmaf(a3, bv.z, acc[3][2]); acc[3][3] = fmaf(a3, bv.w, acc[3][3]);
        }
        __syncthreads();
    }
    #pragma unroll
    for (int i = 0; i < 4; i++) {
        int r = bm + row0 + i;
        if (r >= M) break;
        #pragma unroll
        for (int j = 0; j < 4; j++) {
            float v = acc[i][j] + bias[bn + col0 + j];
            if (doRelu) v = fmaxf(v, 0.f);
            C[(size_t)r * N + bn + col0 + j] = v;
        }
    }
}

// ---------------- persistent 16-CTA-cluster LSTM (round-9 structure + MUFU.TANH gates) ----
// CTA r owns hidden indices [r*16, r*16+16) and gate cols {g*256 + r*16 + j}.
// 512 threads: warp w lane l -> local col lc = w*4+(l&3) (64 cols), k-slice l>>2 (8x32k).
// smem: 2 h-buffers (8 padded slices x 36 words), 2 mbarriers, pa double-buffered.
#define HPAD    36
#define HBUFW   (8 * HPAD)          /* 288 words */
#define HBYTES  (HBUFW * 4)         /* 1152 B    */
#define BAROFF  (2 * HBYTES)        /* 2304      */
#define PAOFF   (BAROFF + 16)       /* 2320      */
#define SMBYTES (PAOFF + 2 * 64 * 4)

__global__ __launch_bounds__(512, 1)
void k_lstm(const float* __restrict__ zs, const int* __restrict__ rowidx,
            const float* __restrict__ W_hh, float* __restrict__ hs)
{
    __shared__ __align__(16) unsigned char sm[SMBYTES];
    float* smf = reinterpret_cast<float*>(sm);

    const int t = threadIdx.x;
    const int l = t & 31;
    const int w = t >> 5;
    const int lc   = w * 4 + (l & 3);   // local gate-col 0..63
    const int ksl  = l >> 2;            // k-slice 0..7 (32 k each)
    const int gate = lc >> 4;
    const int j    = lc & 15;
    const uint32_t rank = ctarank();
    const int base = rank * 16;
    const int gcol = gate * 256 + base + j;

    // resident packed W_hh slice: 16 f32x2 regs (32 k-values for this col)
    unsigned long long w2[16];
    #pragma unroll
    for (int q = 0; q < 16; q++)
        w2[q] = pack_f32x2(W_hh[(size_t)(ksl * 32 + 2 * q) * 1024 + gcol],
                           W_hh[(size_t)(ksl * 32 + 2 * q + 1) * 1024 + gcol]);

    // zero both h buffers (incl. padding)
    for (int i = t; i < 2 * HBUFW; i += 512) smf[i] = 0.f;

    const uint32_t smb = smem_u32(sm);
    if (t == 0) {
        mbar_init(smb + BAROFF, 1);
        mbar_init(smb + BAROFF + 8, 1);
        mbar_arrive_expect_tx(smb + BAROFF, 1024);      // 16 CTAs x 16 floats
        mbar_arrive_expect_tx(smb + BAROFF + 8, 1024);
        asm volatile("fence.mbarrier_init.release.cluster;" ::: "memory");
    }
    __syncthreads();
    asm volatile("barrier.cluster.arrive.aligned;" ::: "memory");
    asm volatile("barrier.cluster.wait.aligned;" ::: "memory");

    // fan-out: thread t<256 owns col hj=t&15, sends to rank t>>4 (16 lanes of a
    // half-warp -> same rank, contiguous words -> coalesced 64B DSMEM writes)
    const int hj = t & 15;
    uint32_t rdst = 0;
    if (t < 256) rdst = mapa_u32(smb, (uint32_t)(t >> 4));
    // padded word offset of my h value (global idx base+hj) inside any h buffer
    const uint32_t myoff = 4u * ((rank >> 1) * HPAD + (rank & 1) * 16 + (uint32_t)hj);

    float c = 0.f;                 // cell state for col base+hj (replicated x16 threads)
    uint32_t ph0 = 0, ph1 = 0;

    for (int step = 0; step < TSTEPS; step++) {
        // prefetch z gate values (independent of h; hidden under the wait's poll)
        float z0 = 0.f, z1 = 0.f, z2 = 0.f, z3 = 0.f;
        if (t < 256) {
            int row = (step == NAGENTS) ? 1024 : __ldg(&rowidx[step]);
            const float* zr = zs + (size_t)row * 1024 + base + hj;
            z0 = __ldg(zr);
            z1 = __ldg(zr + 256);
            z2 = __ldg(zr + 512);
            z3 = __ldg(zr + 768);
        }

        const int buf = step & 1;
        if (step > 0) {            // wait for h(step-1) fan-in (CTA-scope acquire)
            if (buf) { mbar_wait(smb + BAROFF + 8, ph1); ph1 ^= 1; }
            else     { mbar_wait(smb + BAROFF, ph0); ph0 ^= 1; }
            if (t == 0) mbar_arrive_expect_tx(smb + BAROFF + (buf ? 8 : 0), 1024);
        }

        // matvec: 32 k for (col, slice); padded slices (144B apart) -> conflict-free LDS.128
        const ulonglong2* hp = reinterpret_cast<const ulonglong2*>(
            sm + buf * HBYTES + ksl * (HPAD * 4));
        unsigned long long a0 = 0ull, a1 = 0ull;
        #pragma unroll
        for (int q = 0; q < 4; q++) {
            ulonglong2 ha = hp[2 * q];
            ulonglong2 hb = hp[2 * q + 1];
            FFMA2(a0, ha.x, w2[4 * q + 0]);
            FFMA2(a1, ha.y, w2[4 * q + 1]);
            FFMA2(a0, hb.x, w2[4 * q + 2]);
            FFMA2(a1, hb.y, w2[4 * q + 3]);
        }
        float2 f0 = unpack_f32x2(a0), f1 = unpack_f32x2(a1);
        float v = (f0.x + f0.y) + (f1.x + f1.y);
        // reduce across the 8 k-slices (lane bits 2,3,4)
        v += __shfl_xor_sync(0xffffffffu, v, 4);
        v += __shfl_xor_sync(0xffffffffu, v, 8);
        v += __shfl_xor_sync(0xffffffffu, v, 16);
        if (l < 4) smf[(PAOFF >> 2) + buf * 64 + j * 4 + gate] = v;  // pa[buf][j][gate]
        __syncthreads();                                              // one bar per step

        if (t < 256) {
            float4 g4 = *reinterpret_cast<const float4*>(
                &smf[(PAOFF >> 2) + buf * 64 + hj * 4]);
            float zi = g4.x + z0, zf = g4.y + z1, zg = g4.z + z2, zo = g4.w + z3;
            c = fsig_fast(zf) * c + fsig_fast(zi) * ftanh_fast(zg);
            float h = fsig_fast(zo) * ftanh_fast(c);
            if (step + 1 < TSTEPS) {       // each of 256 threads: one st.async
                uint32_t nb = (uint32_t)((step + 1) & 1);
                st_async_b32(rdst + nb * HBYTES + myoff, __float_as_uint(h),
                             rdst + BAROFF + nb * 8u);
            }
            if (t < 16) hs[step * HDIM + base + t] = h;
        }
    }
}

// ---------------- output: softmax(hs@W_act + b_act) ----------------
__global__ __launch_bounds__(256) void k_out(const float* __restrict__ hs,
                                             const float* __restrict__ W,
                                             const float* __restrict__ b,
                                             float* __restrict__ out) {
    __shared__ float hrow[8][HDIM];
    int warp = threadIdx.x >> 5, lane = threadIdx.x & 31;
    int row = blockIdx.x * 8 + warp;
    if (row >= TSTEPS) return;
    #pragma unroll
    for (int q = 0; q < 8; q++)
        hrow[warp][lane + q * 32] = hs[row * HDIM + lane + q * 32];
    __syncwarp();
    int c0 = lane, c1 = lane + 32;
    float acc0 = b[c0], acc1 = b[c1];
    #pragma unroll 8
    for (int k = 0; k < HDIM; k++) {
        float h = hrow[warp][k];
        acc0 = fmaf(h, __ldg(&W[k * ODIM + c0]), acc0);
        acc1 = fmaf(h, __ldg(&W[k * ODIM + c1]), acc1);
    }
    float m = fmaxf(acc0, acc1);
    #pragma unroll
    for (int s = 16; s > 0; s >>= 1) m = fmaxf(m, __shfl_xor_sync(0xffffffffu, m, s));
    float e0 = __expf(acc0 - m), e1 = __expf(acc1 - m);
    float s = e0 + e1;
    #pragma unroll
    for (int d = 16; d > 0; d >>= 1) s += __shfl_xor_sync(0xffffffffu, s, d);
    float inv = __fdividef(1.0f, s);
    out[row * ODIM + c0] = e0 * inv;
    out[row * ODIM + c1] = e1 * inv;
}

// ---------------- launch ----------------
extern "C" void kernel_launch(void* const* d_in, const int* in_sizes, int n_in,
                              void* d_out, int out_size) {
    const float* agent_state = (const float*)d_in[0];
    const float* goal_state  = (const float*)d_in[1];
    const int*   groups      = (const int*)  d_in[2];
    const float* W_goal      = (const float*)d_in[3];
    const float* b_goal      = (const float*)d_in[4];
    const float* W_g1        = (const float*)d_in[5];
    const float* b_g1        = (const float*)d_in[6];
    const float* W_g2        = (const float*)d_in[7];
    const float* b_g2        = (const float*)d_in[8];
    const float* W_ih        = (const float*)d_in[9];
    const float* W_hh        = (const float*)d_in[10];
    const float* b_lstm      = (const float*)d_in[11];
    const float* W_act       = (const float*)d_in[12];
    const float* b_act       = (const float*)d_in[13];
    float* out = (float*)d_out;

    float *X, *Y, *R, *ZS, *HS; int* RI;
    cudaGetSymbolAddress((void**)&X,  g_X);
    cudaGetSymbolAddress((void**)&Y,  g_Y);
    cudaGetSymbolAddress((void**)&R,  g_R);
    cudaGetSymbolAddress((void**)&ZS, g_zs);
    cudaGetSymbolAddress((void**)&HS, g_hs);
    cudaGetSymbolAddress((void**)&RI, g_rowidx);

    k_goal<<<1, 256>>>(goal_state, W_goal, b_goal, R);
    k_rowidx_init<<<NAGENTS / 256, 256>>>(RI);
    k_rowidx_scatter<<<NGROUPS * GSIZE / 256, 256>>>(groups, RI);

    k_group<1><<<NGROUPS, 256>>>(agent_state, groups, X);                 // U1
    k_gemm<<<dim3(4, 512), 256>>>(X, W_g1, b_g1, Y, NAGENTS, HDIM, HDIM, 1);   // H1
    k_group<0><<<NGROUPS, 256>>>(Y, nullptr, X);                          // U2
    k_gemm<<<dim3(4, 512), 256>>>(X, W_g2, b_g2, Y, NAGENTS, HDIM, HDIM, 1);   // H2
    k_pool<<<NGROUPS, 256>>>(Y, R);

    k_gemm<<<dim3(16, 17), 256>>>(R, W_ih, b_lstm, ZS, ZROWS, 1024, HDIM, 0);  // zs

    // 16-CTA cluster LSTM (nonportable cluster size)
    cudaFuncSetAttribute(k_lstm, cudaFuncAttributeNonPortableClusterSizeAllowed, 1);
    {
        cudaLaunchConfig_t cfg = {};
        cfg.gridDim  = dim3(16, 1, 1);
        cfg.blockDim = dim3(512, 1, 1);
        cfg.dynamicSmemBytes = 0;
        cfg.stream = 0;
        cudaLaunchAttribute at[1];
        at[0].id = cudaLaunchAttributeClusterDimension;
        at[0].val.clusterDim.x = 16;
        at[0].val.clusterDim.y = 1;
        at[0].val.clusterDim.z = 1;
        cfg.attrs = at;
        cfg.numAttrs = 1;
        cudaLaunchKernelEx(&cfg, k_lstm, (const float*)ZS, (const int*)RI, W_hh, (float*)HS);
    }

    k_out<<<(TSTEPS + 7) / 8, 256>>>(HS, W_act, b_act, out);
}